// round 12
// baseline (speedup 1.0000x reference)
#include <cuda_runtime.h>

#define CIN   128
#define COUT  64
#define HIN   64
#define WIN   64
#define BATCH 8
#define HO    129
#define WO    129

// Repacked weights: [c][kh][kw][o]  (o fastest -> coalesced shared-tile loads)
__device__ float g_wT[CIN * 9 * COUT];

__global__ void repack_w_kernel(const float* __restrict__ w) {
    int idx = blockIdx.x * blockDim.x + threadIdx.x;   // over CIN*9*COUT
    if (idx < CIN * 9 * COUT) {
        int o = idx & 63;
        int p = idx >> 6;                              // c*9 + kh*3 + kw
        g_wT[idx] = w[o * (CIN * 9) + p];
    }
}

__device__ __forceinline__ void fma2(unsigned long long& d, unsigned long long a, unsigned long long b) {
    asm("fma.rn.f32x2 %0, %1, %2, %0;" : "+l"(d) : "l"(a), "l"(b));
}
__device__ __forceinline__ float2 unpack2(unsigned long long v) {
    float lo, hi;
    asm("mov.b64 {%0, %1}, %2;" : "=f"(lo), "=f"(hi) : "l"(v));
    return make_float2(lo, hi);
}

// One parity class: outputs i = 2a+PI, j = 2b'+PJ. Rows FLATTENED over
// (batch, a); batch-seam halo rows are zero from both sides (see R2 notes).
// X tile stored DUPLICATED as float2(v,v) so the f32x2 FMA operand is one
// aligned LDS.64 (no register-pair-building MOVs).
// Column tiles cover b' in [0,64); column b'=64 (j=128) of the NB=65 classes
// is produced by the strip path (kw=0 tap only).
template<int PI, int PJ, int NAR, int NB>
__device__ __forceinline__ void convt_body(
    const float* __restrict__ x, float* __restrict__ y,
    float2 (&Xs2)[8][17][18], float (&Ws)[8][4][COUT], int (&rowbase)[17],
    int tr, int tc)
{
    constexpr int NH = (PI == 0) ? 2 : 1;
    constexpr int NW = (PJ == 0) ? 2 : 1;
    constexpr int NT = NH * NW;
    constexpr int FTOT = BATCH * NAR;   // flat row count
    constexpr int KC = 8;

    const int f0 = tr * 16;
    const int b0 = tc * 16;
    const int tx = threadIdx.x;
    const int og = tx >> 5;                   // warp id -> o base og*8 (broadcast W in warp)
    const int pg = tx & 31;
    const int cb = pg & 15;                   // column within tile (16 cols across warp)
    const int rg = (pg >> 4) * 8;             // row-group base (0 or 8), 8 rows per thread

    // ---- per-block row table: global x element offset of each shared row, -1 if pad
    if (tx < 17) {
        int p   = (PI == 0) ? (f0 + tx) : (f0 + tx - 1);
        int b   = p / NAR;                    // p >= -1; guarded below
        int ain = p - b * NAR - ((PI == 0) ? 1 : 0);
        bool ok = (p >= 0) && (b < BATCH) && (ain >= 0) && (ain < HIN);
        rowbase[tx] = ok ? ((b * CIN + 0) * HIN * WIN + ain * WIN) : -1;
    }
    __syncthreads();

    unsigned long long acc[4][8];             // [o-pair][row v]
#pragma unroll
    for (int k2 = 0; k2 < 4; k2++)
#pragma unroll
        for (int v = 0; v < 8; v++) acc[k2][v] = 0ULL;

    for (int c0 = 0; c0 < CIN; c0 += KC) {
        // ---- load X tile (17 rows x 17 cols, zero-padded, DUPLICATED)
        for (int idx = tx; idx < KC * 17 * 17; idx += 256) {
            int cc  = idx / (17 * 17);
            int rem = idx - cc * (17 * 17);
            int rr  = rem / 17;
            int cl  = rem - rr * 17;
            int rb  = rowbase[rr];
            int gc  = b0 - 1 + cl;
            float v = 0.f;
            if (rb >= 0 && (unsigned)gc < WIN)
                v = x[rb + (c0 + cc) * (HIN * WIN) + gc];
            Xs2[cc][rr][cl] = make_float2(v, v);
        }
        // ---- load W tile from repacked layout (o-contiguous -> coalesced)
        for (int idx = tx; idx < KC * NT * COUT; idx += 256) {
            int cc  = idx / (NT * COUT);
            int rem = idx - cc * (NT * COUT);
            int t   = rem >> 6;
            int o   = rem & 63;
            int th  = t / NW, tw = t % NW;
            int kh  = (PI == 0) ? th * 2 : 1;
            int kw  = (PJ == 0) ? tw * 2 : 1;
            Ws[cc][t][o] = g_wT[((c0 + cc) * 9 + kh * 3 + kw) * COUT + o];
        }
        __syncthreads();

#pragma unroll 4
        for (int cc = 0; cc < KC; cc++) {
#pragma unroll
            for (int t = 0; t < NT; t++) {
                const int th = t / NW, tw = t % NW;
                const int dr = (PI == 0) ? th : 1;
                const int dc = (PJ == 0) ? tw : 1;
                unsigned long long xd[8];
#pragma unroll
                for (int v = 0; v < 8; v++)
                    xd[v] = *reinterpret_cast<const unsigned long long*>(
                        &Xs2[cc][rg + v + dr][cb + dc]);            // LDS.64, (x,x)
                const unsigned long long* wrow =
                    reinterpret_cast<const unsigned long long*>(&Ws[cc][t][og * 8]);
#pragma unroll
                for (int k2 = 0; k2 < 4; k2++) {
                    unsigned long long w2 = wrow[k2];
#pragma unroll
                    for (int v = 0; v < 8; v++)
                        fma2(acc[k2][v], w2, xd[v]);
                }
            }
        }
        __syncthreads();
    }

    // ---- store: decode flat row -> (batch, a); j stride-2 within class
    const int obase = og * 8;
    const int col   = b0 + cb;
    if (col < NB) {
        const int j = 2 * col + PJ;
#pragma unroll
        for (int v = 0; v < 8; v++) {
            int f = f0 + rg + v;
            if (f < FTOT) {
                int bb = f / NAR;
                int a  = f - bb * NAR;
                int i  = 2 * a + PI;
#pragma unroll
                for (int k2 = 0; k2 < 4; k2++) {
                    float2 p = unpack2(acc[k2][v]);
                    int o = obase + 2 * k2;
                    y[(((size_t)bb * COUT + o) * HO + i) * WO + j]     = p.x;
                    y[(((size_t)bb * COUT + o + 1) * HO + i) * WO + j] = p.y;
                }
            }
        }
    }
}

// Boundary strip path: y[b, o, i, 128]. j=128 admits only kw=0 (kw=2 -> input
// col 64 OOB), against input col 63.
//   even i=2a : kh=0 -> row a-1 (pad if a==0), kh=2 -> row a (invalid if a==64)
//   odd  i=2a+1: kh=1 -> row a
// One 256-thread block handles 4 consecutive (bb,i) pairs (sub = tx/64).
__device__ __forceinline__ void strip_body(
    const float* __restrict__ x, float* __restrict__ y,
    float* sbuf /* >= 4*256 floats */, int t)
{
    const int tx   = threadIdx.x;
    const int sub  = tx >> 6;
    const int o    = tx & 63;
    const int flat = t * 4 + sub;        // 0 .. BATCH*HO-1
    const int bb   = flat / HO;
    const int i    = flat - bb * HO;
    const int a    = i >> 1;
    const bool odd = (i & 1) != 0;
    const int r0 = odd ? a : a - 1;      // kh=1 (odd) / kh=0 (even)
    const int r1 = a;                    // kh=2 (even only)

    float* xs0 = sbuf + sub * 256;
    float* xs1 = xs0 + 128;

    for (int c = o; c < CIN; c += 64) {
        const float* xb = x + ((size_t)bb * CIN + c) * (HIN * WIN) + (WIN - 1);
        xs0[c] = ((unsigned)r0 < HIN) ? xb[r0 * WIN] : 0.f;
        xs1[c] = (!odd && (unsigned)r1 < HIN) ? xb[r1 * WIN] : 0.f;
    }
    __syncthreads();

    float acc = 0.f;
    if (odd) {
        for (int c = 0; c < CIN; c++)
            acc += g_wT[(c * 9 + 3) * COUT + o] * xs0[c];       // kh=1, kw=0
    } else {
        float acc2 = 0.f;
        for (int c = 0; c < CIN; c++) {
            acc  += g_wT[(c * 9 + 0) * COUT + o] * xs0[c];      // kh=0, kw=0
            acc2 += g_wT[(c * 9 + 6) * COUT + o] * xs1[c];      // kh=2, kw=0
        }
        acc += acc2;
    }
    y[(((size_t)bb * COUT + o) * HO + i) * WO + (WO - 1)] = acc;
}

// Block map:
//   [  0,132) class0 (0,0): 33 row-tiles x 4 col-tiles
//   [132,264) class1 (0,1): 33 x 4
//   [264,392) class2 (1,0): 32 x 4
//   [392,520) class3 (1,1): 32 x 4
//   [520,778) strip: 258 blocks x 4 (bb,i) pairs = 1032 = BATCH*HO
#define NBLK 778

__global__ void __launch_bounds__(256)
convt_all_kernel(const float* __restrict__ x, float* __restrict__ y)
{
    __shared__ __align__(16) float2 Xs2[8][17][18];
    __shared__ __align__(16) float  Ws[8][4][COUT];
    __shared__ int rowbase[17];
    const int bid = blockIdx.x;
    if (bid < 132) {
        convt_body<0,0,65,65>(x, y, Xs2, Ws, rowbase, bid / 4, bid % 4);
    } else if (bid < 264) {
        int t = bid - 132;
        convt_body<0,1,65,64>(x, y, Xs2, Ws, rowbase, t / 4, t % 4);
    } else if (bid < 392) {
        int t = bid - 264;
        convt_body<1,0,64,65>(x, y, Xs2, Ws, rowbase, t / 4, t % 4);
    } else if (bid < 520) {
        int t = bid - 392;
        convt_body<1,1,64,64>(x, y, Xs2, Ws, rowbase, t / 4, t % 4);
    } else {
        strip_body(x, y, reinterpret_cast<float*>(Xs2), bid - 520);
    }
}

extern "C" void kernel_launch(void* const* d_in, const int* in_sizes, int n_in,
                              void* d_out, int out_size) {
    const float* x = (const float*)d_in[0];
    const float* w = (const float*)d_in[1];
    // defensive: identify weight by its element count
    if (n_in >= 2 && in_sizes[0] == COUT * CIN * 9) {
        const float* t = x; x = w; w = t;
    }
    float* y = (float*)d_out;

    repack_w_kernel<<<(CIN * 9 * COUT + 255) / 256, 256>>>(w);
    convt_all_kernel<<<NBLK, 256>>>(x, y);
}

// round 13
// speedup vs baseline: 1.2342x; 1.2342x over previous
#include <cuda_runtime.h>

#define CIN   128
#define COUT  64
#define HIN   64
#define WIN   64
#define BATCH 8
#define HO    129
#define WO    129

// Repacked weights: [c][kh][kw][o]  (o fastest -> coalesced shared-tile loads)
__device__ float g_wT[CIN * 9 * COUT];

__global__ void repack_w_kernel(const float* __restrict__ w) {
    int idx = blockIdx.x * blockDim.x + threadIdx.x;   // over CIN*9*COUT
    if (idx < CIN * 9 * COUT) {
        int o = idx & 63;
        int p = idx >> 6;                              // c*9 + kh*3 + kw
        g_wT[idx] = w[o * (CIN * 9) + p];
    }
}

__device__ __forceinline__ void fma2(unsigned long long& d, unsigned long long a, unsigned long long b) {
    asm("fma.rn.f32x2 %0, %1, %2, %0;" : "+l"(d) : "l"(a), "l"(b));
}
__device__ __forceinline__ float2 unpack2(unsigned long long v) {
    float lo, hi;
    asm("mov.b64 {%0, %1}, %2;" : "=f"(lo), "=f"(hi) : "l"(v));
    return make_float2(lo, hi);
}

// One parity class: outputs i = 2a+PI, j = 2b'+PJ. Rows FLATTENED over
// (batch, a); batch-seam halo rows are zero from both sides (see R2 notes).
// 8-row tiles (divide FTOT exactly: 520=65*8, 512=64*8). Micro-tile 4 rows x
// 8 o per thread (acc = 32 regs) so 4 CTAs/SM fit -> 32 warps resident.
// X tile stored DUPLICATED as float2(v,v): f32x2 FMA operand = one LDS.64.
// Row-tap sharing: dr=0/1 taps read overlapping rows; load the union once.
// Column tiles cover b' in [0,64); b'=64 (j=128) handled by strip path.
template<int PI, int PJ, int NAR, int NB>
__device__ __forceinline__ void convt_body(
    const float* __restrict__ x, float* __restrict__ y,
    float2 (&Xs2)[8][9][18], float (&Ws)[8][4][COUT], int (&rowbase)[9],
    int tr, int tc)
{
    constexpr int NH = (PI == 0) ? 2 : 1;
    constexpr int NW = (PJ == 0) ? 2 : 1;
    constexpr int FTOT = BATCH * NAR;   // flat row count
    constexpr int KC = 8;
    constexpr int NU = 3 + NH;          // union rows per thread: 5 (PI=0) / 4 (PI=1)
    constexpr int RB = (PI == 0) ? 0 : 1;  // xdu[u] holds shared row rg+RB+u

    const int f0 = tr * 8;
    const int b0 = tc * 16;
    const int tx = threadIdx.x;
    const int og = tx >> 5;                   // warp id -> o base og*8 (broadcast W in warp)
    const int pg = tx & 31;
    const int cb = pg & 15;                   // column within tile (16 cols across warp)
    const int rg = (pg >> 4) * 4;             // row-quarter base (0 or 4), 4 rows/thread

    // ---- per-block row table: global x element offset of each shared row, -1 if pad
    if (tx < 9) {
        int p   = (PI == 0) ? (f0 + tx) : (f0 + tx - 1);
        int b   = p / NAR;                    // p >= -1; guarded below
        int ain = p - b * NAR - ((PI == 0) ? 1 : 0);
        bool ok = (p >= 0) && (b < BATCH) && (ain >= 0) && (ain < HIN);
        rowbase[tx] = ok ? (b * CIN * HIN * WIN + ain * WIN) : -1;
    }
    __syncthreads();

    unsigned long long acc[4][4];             // [o-pair][row v]
#pragma unroll
    for (int k2 = 0; k2 < 4; k2++)
#pragma unroll
        for (int v = 0; v < 4; v++) acc[k2][v] = 0ULL;

    for (int c0 = 0; c0 < CIN; c0 += KC) {
        // ---- load X tile (9 rows x 17 cols, zero-padded, DUPLICATED)
        for (int idx = tx; idx < KC * 9 * 17; idx += 256) {
            int cc  = idx / (9 * 17);
            int rem = idx - cc * (9 * 17);
            int rr  = rem / 17;
            int cl  = rem - rr * 17;
            int rb  = rowbase[rr];
            int gc  = b0 - 1 + cl;
            float v = 0.f;
            if (rb >= 0 && (unsigned)gc < WIN)
                v = x[rb + (c0 + cc) * (HIN * WIN) + gc];
            Xs2[cc][rr][cl] = make_float2(v, v);
        }
        // ---- load W tile from repacked layout (o-contiguous -> coalesced)
        for (int idx = tx; idx < KC * NH * NW * COUT; idx += 256) {
            int cc  = idx / (NH * NW * COUT);
            int rem = idx - cc * (NH * NW * COUT);
            int t   = rem >> 6;
            int o   = rem & 63;
            int th  = t / NW, tw = t % NW;
            int kh  = (PI == 0) ? th * 2 : 1;
            int kw  = (PJ == 0) ? tw * 2 : 1;
            Ws[cc][t][o] = g_wT[((c0 + cc) * 9 + kh * 3 + kw) * COUT + o];
        }
        __syncthreads();

#pragma unroll 4
        for (int cc = 0; cc < KC; cc++) {
#pragma unroll
            for (int tw = 0; tw < NW; tw++) {
                const int dc = (PJ == 0) ? tw : 1;
                unsigned long long xdu[NU];           // union rows rg+RB .. rg+RB+NU-1
#pragma unroll
                for (int u = 0; u < NU; u++)
                    xdu[u] = *reinterpret_cast<const unsigned long long*>(
                        &Xs2[cc][rg + RB + u][cb + dc]);   // LDS.64, (x,x)
#pragma unroll
                for (int th = 0; th < NH; th++) {
                    const int t = th * NW + tw;
                    const unsigned long long* wrow =
                        reinterpret_cast<const unsigned long long*>(&Ws[cc][t][og * 8]);
#pragma unroll
                    for (int k2 = 0; k2 < 4; k2++) {
                        unsigned long long w2 = wrow[k2];
#pragma unroll
                        for (int v = 0; v < 4; v++)
                            fma2(acc[k2][v], w2, xdu[v + th]);  // row rg+v+dr
                    }
                }
            }
        }
        __syncthreads();
    }

    // ---- store: decode flat row -> (batch, a); j stride-2 within class
    const int obase = og * 8;
    const int col   = b0 + cb;
    if (col < NB) {
        const int j = 2 * col + PJ;
#pragma unroll
        for (int v = 0; v < 4; v++) {
            int f = f0 + rg + v;
            if (f < FTOT) {
                int bb = f / NAR;
                int a  = f - bb * NAR;
                int i  = 2 * a + PI;
#pragma unroll
                for (int k2 = 0; k2 < 4; k2++) {
                    float2 p = unpack2(acc[k2][v]);
                    int o = obase + 2 * k2;
                    y[(((size_t)bb * COUT + o) * HO + i) * WO + j]     = p.x;
                    y[(((size_t)bb * COUT + o + 1) * HO + i) * WO + j] = p.y;
                }
            }
        }
    }
}

// Boundary strip path: y[b, o, i, 128]. j=128 admits only kw=0 (kw=2 -> input
// col 64 OOB), against input col 63.
//   even i=2a : kh=0 -> row a-1 (pad if a==0), kh=2 -> row a (invalid if a==64)
//   odd  i=2a+1: kh=1 -> row a
// One 256-thread block handles 4 consecutive (bb,i) pairs (sub = tx/64).
__device__ __forceinline__ void strip_body(
    const float* __restrict__ x, float* __restrict__ y,
    float* sbuf /* >= 4*256 floats */, int t)
{
    const int tx   = threadIdx.x;
    const int sub  = tx >> 6;
    const int o    = tx & 63;
    const int flat = t * 4 + sub;        // 0 .. BATCH*HO-1
    const int bb   = flat / HO;
    const int i    = flat - bb * HO;
    const int a    = i >> 1;
    const bool odd = (i & 1) != 0;
    const int r0 = odd ? a : a - 1;      // kh=1 (odd) / kh=0 (even)
    const int r1 = a;                    // kh=2 (even only)

    float* xs0 = sbuf + sub * 256;
    float* xs1 = xs0 + 128;

    for (int c = o; c < CIN; c += 64) {
        const float* xb = x + ((size_t)bb * CIN + c) * (HIN * WIN) + (WIN - 1);
        xs0[c] = ((unsigned)r0 < HIN) ? xb[r0 * WIN] : 0.f;
        xs1[c] = (!odd && (unsigned)r1 < HIN) ? xb[r1 * WIN] : 0.f;
    }
    __syncthreads();

    float acc = 0.f;
    if (odd) {
        for (int c = 0; c < CIN; c++)
            acc += g_wT[(c * 9 + 3) * COUT + o] * xs0[c];       // kh=1, kw=0
    } else {
        float acc2 = 0.f;
        for (int c = 0; c < CIN; c++) {
            acc  += g_wT[(c * 9 + 0) * COUT + o] * xs0[c];      // kh=0, kw=0
            acc2 += g_wT[(c * 9 + 6) * COUT + o] * xs1[c];      // kh=2, kw=0
        }
        acc += acc2;
    }
    y[(((size_t)bb * COUT + o) * HO + i) * WO + (WO - 1)] = acc;
}

// Block map (8-row tiles; 65 row-tiles for NAR=65, 64 for NAR=64; 4 col-tiles):
//   [   0, 260) class0 (0,0): 65 x 4
//   [ 260, 520) class1 (0,1): 65 x 4
//   [ 520, 776) class2 (1,0): 64 x 4
//   [ 776,1032) class3 (1,1): 64 x 4
//   [1032,1290) strip: 258 blocks x 4 (bb,i) pairs = 1032 = BATCH*HO
#define NBLK 1290

__global__ void __launch_bounds__(256, 4)
convt_all_kernel(const float* __restrict__ x, float* __restrict__ y)
{
    __shared__ __align__(16) float2 Xs2[8][9][18];
    __shared__ __align__(16) float  Ws[8][4][COUT];
    __shared__ int rowbase[9];
    const int bid = blockIdx.x;
    if (bid < 260) {
        convt_body<0,0,65,65>(x, y, Xs2, Ws, rowbase, bid / 4, bid % 4);
    } else if (bid < 520) {
        int t = bid - 260;
        convt_body<0,1,65,64>(x, y, Xs2, Ws, rowbase, t / 4, t % 4);
    } else if (bid < 776) {
        int t = bid - 520;
        convt_body<1,0,64,65>(x, y, Xs2, Ws, rowbase, t / 4, t % 4);
    } else if (bid < 1032) {
        int t = bid - 776;
        convt_body<1,1,64,64>(x, y, Xs2, Ws, rowbase, t / 4, t % 4);
    } else {
        strip_body(x, y, reinterpret_cast<float*>(Xs2), bid - 1032);
    }
}

extern "C" void kernel_launch(void* const* d_in, const int* in_sizes, int n_in,
                              void* d_out, int out_size) {
    const float* x = (const float*)d_in[0];
    const float* w = (const float*)d_in[1];
    // defensive: identify weight by its element count
    if (n_in >= 2 && in_sizes[0] == COUT * CIN * 9) {
        const float* t = x; x = w; w = t;
    }
    float* y = (float*)d_out;

    repack_w_kernel<<<(CIN * 9 * COUT + 255) / 256, 256>>>(w);
    convt_all_kernel<<<NBLK, 256>>>(x, y);
}